// round 12
// baseline (speedup 1.0000x reference)
#include <cuda_runtime.h>
#include <cuda_fp16.h>
#include <cstdint>

// ============================================================================
// KroneckerLinear: y[t] = U^T * X_t * V  (per-token 128x128x128 GEMM pair)
// R12: 2 CTAs per SM (occ 12.5% -> 25%) for cross-CTA phase overlap.
// Smem cut to 96KB: no cp.async staging (X via LDG streaming, hidden by the
// co-resident CTA), T overlaid into the X16 buffer (GEMM1 fully consumes X
// before T-store). No stationary frags; launch_bounds(256,2) caps regs at 128.
// ============================================================================

static constexpr int TOK = 16384;

// smem layout (bytes)
static constexpr int OFF_VT = 0;         // V^T image [n2][m2], 32KB, persistent
static constexpr int OFF_UT = 32768;     // U^T image [n1][m1], 32KB, persistent
static constexpr int OFF_XT = 65536;     // X fp16 [m1][m2], then T [m1][n2], 32KB
static constexpr int SMEM_BYTES = 98304; // 96KB -> 2 CTAs/SM

__device__ __half g_Ut[16384];
__device__ __half g_Vt[16384];

// swizzled half-index of (row r, col k) in a [128x128] fp16 tile (256B rows)
__host__ __device__ __forceinline__ int himg(int r, int k) {
    return r * 128 + (k ^ ((r & 7) << 3));
}

__device__ __forceinline__ uint32_t smem_u32(const void* p) {
    uint32_t a;
    asm("{ .reg .u64 t; cvta.to.shared.u64 t, %1; cvt.u32.u64 %0, t; }"
        : "=r"(a) : "l"(p));
    return a;
}

#define LDMX4(r, addr)                                                        \
    asm volatile("ldmatrix.sync.aligned.m8n8.x4.shared.b16 {%0,%1,%2,%3}, [%4];" \
        : "=r"((r)[0]), "=r"((r)[1]), "=r"((r)[2]), "=r"((r)[3]) : "r"(addr))

#define LDMX4T(r, addr)                                                       \
    asm volatile("ldmatrix.sync.aligned.m8n8.x4.trans.shared.b16 {%0,%1,%2,%3}, [%4];" \
        : "=r"((r)[0]), "=r"((r)[1]), "=r"((r)[2]), "=r"((r)[3]) : "r"(addr))

#define MMA16816(c, a, b0, b1)                                                \
    asm volatile(                                                             \
        "mma.sync.aligned.m16n8k16.row.col.f32.f16.f16.f32 "                  \
        "{%0,%1,%2,%3},{%4,%5,%6,%7},{%8,%9},{%0,%1,%2,%3};"                  \
        : "+f"((c)[0]), "+f"((c)[1]), "+f"((c)[2]), "+f"((c)[3])              \
        : "r"((a)[0]), "r"((a)[1]), "r"((a)[2]), "r"((a)[3]), "r"(b0), "r"(b1))

// ---------------------------------------------------------------------------
__global__ void kron_setup(const float* __restrict__ U, const float* __restrict__ V) {
    int e = blockIdx.x * blockDim.x + threadIdx.x;
    if (e >= 16384) return;
    int n = e >> 7;
    int m = e & 127;
    g_Ut[himg(n, m)] = __float2half_rn(U[m * 128 + n]);
    g_Vt[himg(n, m)] = __float2half_rn(V[m * 128 + n]);
}

// ---------------------------------------------------------------------------
__global__ void __launch_bounds__(256, 2)
kron_main(const float* __restrict__ x, float* __restrict__ out, int ntok) {
    extern __shared__ char smem[];
    const uint32_t sb = smem_u32(smem);
    const int tid = threadIdx.x;
    const int wid = tid >> 5;
    const int lid = tid & 31;
    const int g   = lid >> 2;
    const int tg4 = lid & 3;
    // GEMM1 warp tile 64x32: A rows m1, B rows n2
    const int m0  = (wid & 1) * 64;
    const int n0  = (wid >> 1) * 32;
    // GEMM2 warp tile 32x64: A rows n1 (from UT), B cols n2 (trans T)
    const int m20 = (wid & 3) * 32;
    const int n20 = (wid >> 2) * 64;
    const uint32_t lrow = (uint32_t)(lid & 15);
    const uint32_t lsw  = (uint32_t)((lid & 7) << 4);
    const uint32_t lk   = (uint32_t)(lid & 16);
    const int gstep = (int)gridDim.x;

    __half* xh = reinterpret_cast<__half*>(smem + OFF_XT);
    __half* th = xh;   // T overlays X16 (X fully consumed before T-store)

    // ---- preamble: stage persistent V^T / U^T images ----
    {
        const uint4* us = reinterpret_cast<const uint4*>(g_Ut);
        const uint4* vs = reinterpret_cast<const uint4*>(g_Vt);
        uint4* ud = reinterpret_cast<uint4*>(smem + OFF_UT);
        uint4* vd = reinterpret_cast<uint4*>(smem + OFF_VT);
        #pragma unroll
        for (int i = tid; i < 2048; i += 256) { ud[i] = us[i]; vd[i] = vs[i]; }
    }
    __syncthreads();

    for (int t = blockIdx.x; t < ntok; t += gstep) {
        // ---- stage X: LDG.128 streaming -> swizzled fp16 [m1][m2] ----
        {
            const float4* xs = reinterpret_cast<const float4*>(x + (size_t)t * TOK);
            #pragma unroll
            for (int it = 0; it < 16; it++) {
                int i = tid + it * 256;
                float4 f = __ldcs(&xs[i]);
                int m = i >> 5, k4 = (i & 31) * 4;
                __half2 lo = __floats2half2_rn(f.x, f.y);
                __half2 hi = __floats2half2_rn(f.z, f.w);
                uint2 p;
                p.x = reinterpret_cast<uint32_t&>(lo);
                p.y = reinterpret_cast<uint32_t&>(hi);
                *reinterpret_cast<uint2*>(xh + m * 128 + (k4 ^ ((m & 7) << 3))) = p;
            }
        }
        __syncthreads();

        // ---- GEMM1: T[m1][n2] = sum_m2 X[m1][m2] * V[m2][n2] ----
        float c[4][4][4];
        #pragma unroll
        for (int i = 0; i < 4; i++)
            #pragma unroll
            for (int j = 0; j < 4; j++)
                #pragma unroll
                for (int q = 0; q < 4; q++) c[i][j][q] = 0.f;

        #pragma unroll
        for (int ks = 0; ks < 8; ks++) {
            uint32_t koff = ((uint32_t)(32 * ks) + lk) ^ lsw;
            uint32_t a[4][4], bv[2][4];
            #pragma unroll
            for (int mt = 0; mt < 4; mt++)
                LDMX4(a[mt],
                      sb + OFF_XT + (uint32_t)(m0 + mt * 16 + lrow) * 256u + koff);
            #pragma unroll
            for (int nb = 0; nb < 2; nb++)
                LDMX4(bv[nb],
                      sb + OFF_VT + (uint32_t)(n0 + nb * 16 + lrow) * 256u + koff);
            #pragma unroll
            for (int mt = 0; mt < 4; mt++) {
                MMA16816(c[mt][0], a[mt], bv[0][0], bv[0][2]);
                MMA16816(c[mt][1], a[mt], bv[0][1], bv[0][3]);
                MMA16816(c[mt][2], a[mt], bv[1][0], bv[1][2]);
                MMA16816(c[mt][3], a[mt], bv[1][1], bv[1][3]);
            }
        }
        __syncthreads();   // ALL warps done reading X16 before T overwrites it

        // ---- store T natural [m1][n2] into the same buffer ----
        #pragma unroll
        for (int mt = 0; mt < 4; mt++) {
            #pragma unroll
            for (int nt = 0; nt < 4; nt++) {
                int m1 = m0 + mt * 16 + g;
                int n2 = n0 + nt * 8 + 2 * tg4;
                __half2 lo = __floats2half2_rn(c[mt][nt][0], c[mt][nt][1]);
                __half2 hi = __floats2half2_rn(c[mt][nt][2], c[mt][nt][3]);
                *reinterpret_cast<__half2*>(
                    th + m1 * 128 + (n2 ^ ((m1 & 7) << 3))) = lo;
                *reinterpret_cast<__half2*>(
                    th + (m1 + 8) * 128 + (n2 ^ (((m1 + 8) & 7) << 3))) = hi;
            }
        }
        __syncthreads();

        // ---- GEMM2: Y[n1][n2] = sum_m1 Ut[n1][m1] * T[m1][n2] ----
        // A = UT image (LDMX4); B = ldmatrix.trans from natural T.
        float c2[2][8][4];
        #pragma unroll
        for (int i = 0; i < 2; i++)
            #pragma unroll
            for (int j = 0; j < 8; j++)
                #pragma unroll
                for (int q = 0; q < 4; q++) c2[i][j][q] = 0.f;

        const uint32_t ncol_lane = (uint32_t)n20 + (lk >> 1);
        #pragma unroll
        for (int ks = 0; ks < 8; ks++) {
            uint32_t koff = ((uint32_t)(32 * ks) + lk) ^ lsw;
            uint32_t au[2][4], bf[4][4];
            #pragma unroll
            for (int mt = 0; mt < 2; mt++)
                LDMX4(au[mt],
                      sb + OFF_UT + (uint32_t)(m20 + mt * 16 + lrow) * 256u + koff);
            #pragma unroll
            for (int nb = 0; nb < 4; nb++) {
                uint32_t ncol = ncol_lane + (uint32_t)(nb * 16);
                LDMX4T(bf[nb],
                       sb + OFF_XT + (uint32_t)(16 * ks + (int)lrow) * 256u +
                       ((ncol * 2u) ^ lsw));
            }
            #pragma unroll
            for (int mt = 0; mt < 2; mt++)
                #pragma unroll
                for (int nb = 0; nb < 4; nb++) {
                    MMA16816(c2[mt][2 * nb],     au[mt], bf[nb][0], bf[nb][1]);
                    MMA16816(c2[mt][2 * nb + 1], au[mt], bf[nb][2], bf[nb][3]);
                }
        }

        // ---- epilogue: natural Y, coalesced STG.64 (streaming) ----
        {
            float* o = out + (size_t)t * TOK;
            #pragma unroll
            for (int mt = 0; mt < 2; mt++) {
                int n1 = m20 + mt * 16 + g;
                #pragma unroll
                for (int j = 0; j < 8; j++) {
                    int n2 = n20 + j * 8 + 2 * tg4;
                    __stcs(reinterpret_cast<float2*>(o + n1 * 128 + n2),
                           make_float2(c2[mt][j][0], c2[mt][j][1]));
                    __stcs(reinterpret_cast<float2*>(o + (n1 + 8) * 128 + n2),
                           make_float2(c2[mt][j][2], c2[mt][j][3]));
                }
            }
        }
        __syncthreads();   // T reads done before next token's convert overwrites
    }
}

// ---------------------------------------------------------------------------
extern "C" void kernel_launch(void* const* d_in, const int* in_sizes, int n_in,
                              void* d_out, int out_size) {
    (void)n_in; (void)out_size;
    const float* x = (const float*)d_in[0];
    const float* U = (const float*)d_in[1];
    const float* V = (const float*)d_in[2];
    float* out = (float*)d_out;
    const int ntok = in_sizes[0] / TOK;

    static int sm_count = 0;
    if (sm_count == 0) {
        cudaDeviceGetAttribute(&sm_count, cudaDevAttrMultiProcessorCount, 0);
        if (sm_count <= 0) sm_count = 148;
        cudaFuncSetAttribute(kron_main, cudaFuncAttributeMaxDynamicSharedMemorySize,
                             SMEM_BYTES);
    }
    int grid = 2 * sm_count;
    if (grid > ntok) grid = ntok;

    kron_setup<<<64, 256>>>(U, V);
    kron_main<<<grid, 256, SMEM_BYTES>>>(x, out, ntok);
}

// round 13
// speedup vs baseline: 1.1203x; 1.1203x over previous
#include <cuda_runtime.h>
#include <cuda_fp16.h>
#include <cstdint>

// ============================================================================
// KroneckerLinear: y[t] = U^T * X_t * V  (per-token 128x128x128 GEMM pair)
// R13 = R8 (best: stationary V+U frags, cp.async staging, Y^T epilogue)
// + double-buffered X16/T with reordered schedule: 2 barriers/token (was 3),
// and epilogue+convert overlap GEMM2's tail across warp skew.
// ============================================================================

static constexpr int TOK = 16384;

// smem layout (bytes). X16A/B double buffer (VT/UT images overlay in preamble);
// T double buffer.
static constexpr int OFF_X32  = 0;        // raw fp32 token (cp.async), 64KB
static constexpr int OFF_X16A = 65536;    // X fp16 buf0 / VT image, 32KB
static constexpr int OFF_X16B = 98304;    // X fp16 buf1 / UT image, 32KB
static constexpr int OFF_TA   = 131072;   // T buf0, 32KB
static constexpr int OFF_TB   = 163840;   // T buf1, 32KB
static constexpr int SMEM_BYTES = 196608; // 192KB

__device__ __half g_Ut[16384];
__device__ __half g_Vt[16384];

__host__ __device__ __forceinline__ int himg(int r, int k) {
    return r * 128 + (k ^ ((r & 7) << 3));
}

__device__ __forceinline__ uint32_t smem_u32(const void* p) {
    uint32_t a;
    asm("{ .reg .u64 t; cvta.to.shared.u64 t, %1; cvt.u32.u64 %0, t; }"
        : "=r"(a) : "l"(p));
    return a;
}

#define LDMX4(r, addr)                                                        \
    asm volatile("ldmatrix.sync.aligned.m8n8.x4.shared.b16 {%0,%1,%2,%3}, [%4];" \
        : "=r"((r)[0]), "=r"((r)[1]), "=r"((r)[2]), "=r"((r)[3]) : "r"(addr))

#define LDMX4T(r, addr)                                                       \
    asm volatile("ldmatrix.sync.aligned.m8n8.x4.trans.shared.b16 {%0,%1,%2,%3}, [%4];" \
        : "=r"((r)[0]), "=r"((r)[1]), "=r"((r)[2]), "=r"((r)[3]) : "r"(addr))

#define MMA16816(c, a, b0, b1)                                                \
    asm volatile(                                                             \
        "mma.sync.aligned.m16n8k16.row.col.f32.f16.f16.f32 "                  \
        "{%0,%1,%2,%3},{%4,%5,%6,%7},{%8,%9},{%0,%1,%2,%3};"                  \
        : "+f"((c)[0]), "+f"((c)[1]), "+f"((c)[2]), "+f"((c)[3])              \
        : "r"((a)[0]), "r"((a)[1]), "r"((a)[2]), "r"((a)[3]), "r"(b0), "r"(b1))

#define CP_ASYNC16(saddr, gptr)                                               \
    asm volatile("cp.async.cg.shared.global [%0], [%1], 16;"                  \
        :: "r"(saddr), "l"(gptr))

// ---------------------------------------------------------------------------
__global__ void kron_setup(const float* __restrict__ U, const float* __restrict__ V) {
    int e = blockIdx.x * blockDim.x + threadIdx.x;
    if (e >= 16384) return;
    int n = e >> 7;
    int m = e & 127;
    g_Ut[himg(n, m)] = __float2half_rn(U[m * 128 + n]);
    g_Vt[himg(n, m)] = __float2half_rn(V[m * 128 + n]);
}

// ---------------------------------------------------------------------------
__global__ void __launch_bounds__(256, 1)
kron_main(const float* __restrict__ x, float* __restrict__ out, int ntok) {
    extern __shared__ char smem[];
    const uint32_t sb = smem_u32(smem);
    const int tid = threadIdx.x;
    const int wid = tid >> 5;
    const int lid = tid & 31;
    const int g   = lid >> 2;
    const int tg4 = lid & 3;
    // GEMM1 warp tile 64x32
    const int m0  = (wid & 1) * 64;
    const int n0  = (wid >> 1) * 32;
    // GEMM2 (C = Y^T [n2][n1]): A rows n2 (trans from T), B rows n1 (stationary U)
    const int a20 = (wid & 1) * 64;
    const int b20 = (wid >> 1) * 32;
    const uint32_t lrow = (uint32_t)(lid & 15);
    const uint32_t lsw  = (uint32_t)((lid & 7) << 4);
    const uint32_t lk   = (uint32_t)(lid & 16);
    // trans-A (GEMM2) per-lane addressing
    const uint32_t arow  = (uint32_t)((lid & 7) | ((lid & 16) >> 1));
    const uint32_t acolh = (uint32_t)(lid & 8);
    const int gstep = (int)gridDim.x;

    const uint32_t x32b = sb + OFF_X32;
    const float4*  x32f = reinterpret_cast<const float4*>(smem + OFF_X32);

    // ---- preamble: images into X16 buffers; prefetch first token ----
    {
        const uint4* us = reinterpret_cast<const uint4*>(g_Ut);
        const uint4* vs = reinterpret_cast<const uint4*>(g_Vt);
        uint4* ud = reinterpret_cast<uint4*>(smem + OFF_X16B);
        uint4* vd = reinterpret_cast<uint4*>(smem + OFF_X16A);
        #pragma unroll
        for (int i = tid; i < 2048; i += 256) { ud[i] = us[i]; vd[i] = vs[i]; }
    }
    int t = blockIdx.x;
    if (t < ntok) {
        const char* src = reinterpret_cast<const char*>(x + (size_t)t * TOK);
        #pragma unroll
        for (int it = 0; it < 16; it++) {
            int i = tid + it * 256;
            CP_ASYNC16(x32b + (uint32_t)i * 16u, src + (size_t)i * 16);
        }
    }
    asm volatile("cp.async.commit_group;" ::: "memory");
    __syncthreads();

    // ---- stationary frags: vst (GEMM1-B from VT image), ust (GEMM2-B from UT) ----
    uint32_t vst[8][2][4], ust[8][2][4];
    #pragma unroll
    for (int ks = 0; ks < 8; ks++) {
        uint32_t koff = ((uint32_t)(32 * ks) + lk) ^ lsw;
        #pragma unroll
        for (int nb = 0; nb < 2; nb++) {
            LDMX4(vst[ks][nb],
                  sb + OFF_X16A + (uint32_t)(n0 + nb * 16 + lrow) * 256u + koff);
            LDMX4(ust[ks][nb],
                  sb + OFF_X16B + (uint32_t)(b20 + nb * 16 + lrow) * 256u + koff);
        }
    }
    asm volatile("cp.async.wait_group 0;" ::: "memory");
    __syncthreads();   // frags extracted before X16A is overwritten

    // ---- prologue: convert X(t) -> X16A; sync; issue cp.async X(t+1) ----
    if (t < ntok) {
        __half* xh = reinterpret_cast<__half*>(smem + OFF_X16A);
        #pragma unroll
        for (int it = 0; it < 16; it++) {
            int i = tid + it * 256;
            float4 f = x32f[i];
            int m = i >> 5, k4 = (i & 31) * 4;
            __half2 lo = __floats2half2_rn(f.x, f.y);
            __half2 hi = __floats2half2_rn(f.z, f.w);
            uint2 p;
            p.x = reinterpret_cast<uint32_t&>(lo);
            p.y = reinterpret_cast<uint32_t&>(hi);
            *reinterpret_cast<uint2*>(xh + m * 128 + (k4 ^ ((m & 7) << 3))) = p;
        }
    }
    __syncthreads();
    if (t + gstep < ntok) {
        const char* src = reinterpret_cast<const char*>(x + (size_t)(t + gstep) * TOK);
        #pragma unroll
        for (int it = 0; it < 16; it++) {
            int i = tid + it * 256;
            CP_ASYNC16(x32b + (uint32_t)i * 16u, src + (size_t)i * 16);
        }
    }
    asm volatile("cp.async.commit_group;" ::: "memory");

    uint32_t xoff = 0;   // 0 -> X16A/TA, 32768 -> X16B/TB
    for (; t < ntok; t += gstep, xoff ^= 32768u) {
        const uint32_t Xcur = sb + OFF_X16A + xoff;
        const uint32_t Tcur = sb + OFF_TA + xoff;
        __half* th = reinterpret_cast<__half*>(smem + (OFF_TA + (int)xoff));

        // ---- GEMM1: T[m1][n2] = sum_m2 X[m1][m2] * V[m2][n2] ----
        float c[4][4][4];
        #pragma unroll
        for (int i = 0; i < 4; i++)
            #pragma unroll
            for (int j = 0; j < 4; j++)
                #pragma unroll
                for (int q = 0; q < 4; q++) c[i][j][q] = 0.f;

        #pragma unroll
        for (int ks = 0; ks < 8; ks++) {
            uint32_t koff = ((uint32_t)(32 * ks) + lk) ^ lsw;
            uint32_t a[4][4];
            #pragma unroll
            for (int mt = 0; mt < 4; mt++)
                LDMX4(a[mt], Xcur + (uint32_t)(m0 + mt * 16 + lrow) * 256u + koff);
            #pragma unroll
            for (int mt = 0; mt < 4; mt++) {
                MMA16816(c[mt][0], a[mt], vst[ks][0][0], vst[ks][0][2]);
                MMA16816(c[mt][1], a[mt], vst[ks][0][1], vst[ks][0][3]);
                MMA16816(c[mt][2], a[mt], vst[ks][1][0], vst[ks][1][2]);
                MMA16816(c[mt][3], a[mt], vst[ks][1][1], vst[ks][1][3]);
            }
        }

        // ---- store T natural [m1][n2] (conflict-free STS.32) ----
        #pragma unroll
        for (int mt = 0; mt < 4; mt++) {
            #pragma unroll
            for (int nt = 0; nt < 4; nt++) {
                int m1 = m0 + mt * 16 + g;
                int n2 = n0 + nt * 8 + 2 * tg4;
                __half2 lo = __floats2half2_rn(c[mt][nt][0], c[mt][nt][1]);
                __half2 hi = __floats2half2_rn(c[mt][nt][2], c[mt][nt][3]);
                *reinterpret_cast<__half2*>(
                    th + m1 * 128 + (n2 ^ ((m1 & 7) << 3))) = lo;
                *reinterpret_cast<__half2*>(
                    th + (m1 + 8) * 128 + (n2 ^ (((m1 + 8) & 7) << 3))) = hi;
            }
        }
        __syncthreads();   // barrier 1: T complete

        // ---- GEMM2: Y^T[n2][n1] = sum_m1 T^T[n2][m1] * Ut[n1][m1] ----
        #pragma unroll
        for (int i = 0; i < 4; i++)
            #pragma unroll
            for (int j = 0; j < 4; j++)
                #pragma unroll
                for (int q = 0; q < 4; q++) c[i][j][q] = 0.f;

        #pragma unroll
        for (int ks = 0; ks < 8; ks++) {
            uint32_t a[4][4];
            #pragma unroll
            for (int at = 0; at < 4; at++) {
                uint32_t srow = (uint32_t)(16 * ks) + arow;
                uint32_t scol = (uint32_t)(a20 + at * 16) + acolh;
                LDMX4T(a[at], Tcur + srow * 256u + ((scol * 2u) ^ lsw));
            }
            #pragma unroll
            for (int at = 0; at < 4; at++) {
                MMA16816(c[at][0], a[at], ust[ks][0][0], ust[ks][0][2]);
                MMA16816(c[at][1], a[at], ust[ks][0][1], ust[ks][0][3]);
                MMA16816(c[at][2], a[at], ust[ks][1][0], ust[ks][1][2]);
                MMA16816(c[at][3], a[at], ust[ks][1][1], ust[ks][1][3]);
            }
        }

        // ---- epilogue: C = Y^T[n2][n1] -> out (R8-style scattered STG.32) ----
        {
            float* o = out + (size_t)t * TOK;
            #pragma unroll
            for (int at = 0; at < 4; at++) {
                int n2a = a20 + at * 16 + g;
                #pragma unroll
                for (int bt = 0; bt < 4; bt++) {
                    int n1a = b20 + bt * 8 + 2 * tg4;
                    __stcs(o + n1a * 128 + n2a,           c[at][bt][0]);
                    __stcs(o + (n1a + 1) * 128 + n2a,     c[at][bt][1]);
                    __stcs(o + n1a * 128 + n2a + 8,       c[at][bt][2]);
                    __stcs(o + (n1a + 1) * 128 + n2a + 8, c[at][bt][3]);
                }
            }
        }

        // ---- convert X(t+1) -> X16[other]; sync; issue cp.async X(t+2) ----
        asm volatile("cp.async.wait_group 0;" ::: "memory");
        if (t + gstep < ntok) {
            __half* xh = reinterpret_cast<__half*>(
                smem + OFF_X16A + (int)(xoff ^ 32768u));
            #pragma unroll
            for (int it = 0; it < 16; it++) {
                int i = tid + it * 256;
                float4 f = x32f[i];
                int m = i >> 5, k4 = (i & 31) * 4;
                __half2 lo = __floats2half2_rn(f.x, f.y);
                __half2 hi = __floats2half2_rn(f.z, f.w);
                uint2 p;
                p.x = reinterpret_cast<uint32_t&>(lo);
                p.y = reinterpret_cast<uint32_t&>(hi);
                *reinterpret_cast<uint2*>(xh + m * 128 + (k4 ^ ((m & 7) << 3))) = p;
            }
        }
        __syncthreads();   // barrier 2: X16[other] ready; X32 free
        if (t + 2 * gstep < ntok) {
            const char* src = reinterpret_cast<const char*>(
                x + (size_t)(t + 2 * gstep) * TOK);
            #pragma unroll
            for (int it = 0; it < 16; it++) {
                int i = tid + it * 256;
                CP_ASYNC16(x32b + (uint32_t)i * 16u, src + (size_t)i * 16);
            }
        }
        asm volatile("cp.async.commit_group;" ::: "memory");
    }
}

// ---------------------------------------------------------------------------
extern "C" void kernel_launch(void* const* d_in, const int* in_sizes, int n_in,
                              void* d_out, int out_size) {
    (void)n_in; (void)out_size;
    const float* x = (const float*)d_in[0];
    const float* U = (const float*)d_in[1];
    const float* V = (const float*)d_in[2];
    float* out = (float*)d_out;
    const int ntok = in_sizes[0] / TOK;

    static int sm_count = 0;
    if (sm_count == 0) {
        cudaDeviceGetAttribute(&sm_count, cudaDevAttrMultiProcessorCount, 0);
        if (sm_count <= 0) sm_count = 148;
        cudaFuncSetAttribute(kron_main, cudaFuncAttributeMaxDynamicSharedMemorySize,
                             SMEM_BYTES);
    }
    int grid = sm_count < ntok ? sm_count : ntok;

    kron_setup<<<64, 256>>>(U, V);
    kron_main<<<grid, 256, SMEM_BYTES>>>(x, out, ntok);
}

// round 14
// speedup vs baseline: 1.1926x; 1.0645x over previous
#include <cuda_runtime.h>
#include <cuda_fp16.h>
#include <cstdint>

// ============================================================================
// KroneckerLinear: y[t] = U^T * X_t * V  (per-token 128x128x128 GEMM pair)
// R14 = R8 (best at 64.9us) with GEMM1 switched to fp16 ACCUMULATION:
// T is rounded to fp16 before GEMM2 anyway, so fp16-acc adds only per-mma
// rounding (predicted total rel_err ~7.3e-4 < 1e-3). Frees 32 accumulator
// regs (252 -> ~220, off the spill cliff) and eliminates all T-store cvts
// (acc regs are the half2 pairs the store needs). GEMM2 stays fp32-acc.
// ============================================================================

static constexpr int TOK = 16384;

// smem layout (bytes)
static constexpr int OFF_X32 = 0;         // raw fp32 token (cp.async), 64KB
static constexpr int OFF_X16 = 65536;     // X fp16 swizzled [m1][m2], 32KB
static constexpr int OFF_T   = 98304;     // T image [m1][n2] natural, 32KB
static constexpr int OFF_VT  = 131072;    // V^T image (preamble only), 32KB
static constexpr int OFF_UT  = 163840;    // U^T image (preamble only), 32KB
static constexpr int SMEM_BYTES = 196608; // 192KB

__device__ __half g_Ut[16384];
__device__ __half g_Vt[16384];

__host__ __device__ __forceinline__ int himg(int r, int k) {
    return r * 128 + (k ^ ((r & 7) << 3));
}

__device__ __forceinline__ uint32_t smem_u32(const void* p) {
    uint32_t a;
    asm("{ .reg .u64 t; cvta.to.shared.u64 t, %1; cvt.u32.u64 %0, t; }"
        : "=r"(a) : "l"(p));
    return a;
}

#define LDMX4(r, addr)                                                        \
    asm volatile("ldmatrix.sync.aligned.m8n8.x4.shared.b16 {%0,%1,%2,%3}, [%4];" \
        : "=r"((r)[0]), "=r"((r)[1]), "=r"((r)[2]), "=r"((r)[3]) : "r"(addr))

#define LDMX4T(r, addr)                                                       \
    asm volatile("ldmatrix.sync.aligned.m8n8.x4.trans.shared.b16 {%0,%1,%2,%3}, [%4];" \
        : "=r"((r)[0]), "=r"((r)[1]), "=r"((r)[2]), "=r"((r)[3]) : "r"(addr))

// fp32-accumulate mma (GEMM2)
#define MMA16816(c, a, b0, b1)                                                \
    asm volatile(                                                             \
        "mma.sync.aligned.m16n8k16.row.col.f32.f16.f16.f32 "                  \
        "{%0,%1,%2,%3},{%4,%5,%6,%7},{%8,%9},{%0,%1,%2,%3};"                  \
        : "+f"((c)[0]), "+f"((c)[1]), "+f"((c)[2]), "+f"((c)[3])              \
        : "r"((a)[0]), "r"((a)[1]), "r"((a)[2]), "r"((a)[3]), "r"(b0), "r"(b1))

// fp16-accumulate mma (GEMM1): c = 2x u32 regs (4 halves)
#define MMA16816H(c, a, b0, b1)                                               \
    asm volatile(                                                             \
        "mma.sync.aligned.m16n8k16.row.col.f16.f16.f16.f16 "                  \
        "{%0,%1},{%2,%3,%4,%5},{%6,%7},{%0,%1};"                              \
        : "+r"((c)[0]), "+r"((c)[1])                                          \
        : "r"((a)[0]), "r"((a)[1]), "r"((a)[2]), "r"((a)[3]), "r"(b0), "r"(b1))

#define CP_ASYNC16(saddr, gptr)                                               \
    asm volatile("cp.async.cg.shared.global [%0], [%1], 16;"                  \
        :: "r"(saddr), "l"(gptr))

// ---------------------------------------------------------------------------
__global__ void kron_setup(const float* __restrict__ U, const float* __restrict__ V) {
    int e = blockIdx.x * blockDim.x + threadIdx.x;
    if (e >= 16384) return;
    int n = e >> 7;
    int m = e & 127;
    g_Ut[himg(n, m)] = __float2half_rn(U[m * 128 + n]);
    g_Vt[himg(n, m)] = __float2half_rn(V[m * 128 + n]);
}

// ---------------------------------------------------------------------------
__global__ void __launch_bounds__(256, 1)
kron_main(const float* __restrict__ x, float* __restrict__ out, int ntok) {
    extern __shared__ char smem[];
    const uint32_t sb = smem_u32(smem);
    const int tid = threadIdx.x;
    const int wid = tid >> 5;
    const int lid = tid & 31;
    const int g   = lid >> 2;
    const int tg4 = lid & 3;
    // GEMM1 warp tile 64x32: A rows m1, B rows n2
    const int m0  = (wid & 1) * 64;
    const int n0  = (wid >> 1) * 32;
    // GEMM2 (C = Y^T [n2][n1]): A rows n2 (trans from T), B rows n1 (stationary U)
    const int a20 = (wid & 1) * 64;
    const int b20 = (wid >> 1) * 32;
    const uint32_t lrow = (uint32_t)(lid & 15);
    const uint32_t lsw  = (uint32_t)((lid & 7) << 4);
    const uint32_t lk   = (uint32_t)(lid & 16);
    // trans-A (GEMM2) per-lane addressing
    const uint32_t arow  = (uint32_t)((lid & 7) | ((lid & 16) >> 1));
    const uint32_t acolh = (uint32_t)(lid & 8);
    const int gstep = (int)gridDim.x;

    const uint32_t x32b = sb + OFF_X32;
    const float4*  x32f = reinterpret_cast<const float4*>(smem + OFF_X32);
    __half* xh = reinterpret_cast<__half*>(smem + OFF_X16);
    __half* th = reinterpret_cast<__half*>(smem + OFF_T);

    // ---- preamble: stage U^T / V^T images; prefetch first token ----
    {
        const uint4* us = reinterpret_cast<const uint4*>(g_Ut);
        const uint4* vs = reinterpret_cast<const uint4*>(g_Vt);
        uint4* ud = reinterpret_cast<uint4*>(smem + OFF_UT);
        uint4* vd = reinterpret_cast<uint4*>(smem + OFF_VT);
        #pragma unroll
        for (int i = tid; i < 2048; i += 256) { ud[i] = us[i]; vd[i] = vs[i]; }
    }
    int t = blockIdx.x;
    if (t < ntok) {
        const char* src = reinterpret_cast<const char*>(x + (size_t)t * TOK);
        #pragma unroll
        for (int it = 0; it < 16; it++) {
            int i = tid + it * 256;
            CP_ASYNC16(x32b + (uint32_t)i * 16u, src + (size_t)i * 16);
        }
    }
    asm volatile("cp.async.commit_group;" ::: "memory");
    __syncthreads();

    // ---- preload stationary fragments ----
    // vst: GEMM1 B-side (V^T rows n0..+31). ust: GEMM2 B-side (U^T rows b20..+31).
    uint32_t vst[8][2][4], ust[8][2][4];
    #pragma unroll
    for (int ks = 0; ks < 8; ks++) {
        uint32_t koff = ((uint32_t)(32 * ks) + lk) ^ lsw;
        #pragma unroll
        for (int nb = 0; nb < 2; nb++) {
            LDMX4(vst[ks][nb],
                  sb + OFF_VT + (uint32_t)(n0 + nb * 16 + lrow) * 256u + koff);
            LDMX4(ust[ks][nb],
                  sb + OFF_UT + (uint32_t)(b20 + nb * 16 + lrow) * 256u + koff);
        }
    }

    asm volatile("cp.async.wait_group 0;" ::: "memory");
    __syncthreads();

    for (; t < ntok; t += gstep) {
        // ---- convert X32 -> X16 (swizzled fp16 [m1][m2]) ----
        #pragma unroll
        for (int it = 0; it < 16; it++) {
            int i = tid + it * 256;
            float4 f = x32f[i];
            int m = i >> 5, k4 = (i & 31) * 4;
            __half2 lo = __floats2half2_rn(f.x, f.y);
            __half2 hi = __floats2half2_rn(f.z, f.w);
            uint2 p;
            p.x = reinterpret_cast<uint32_t&>(lo);
            p.y = reinterpret_cast<uint32_t&>(hi);
            *reinterpret_cast<uint2*>(xh + m * 128 + (k4 ^ ((m & 7) << 3))) = p;
        }
        __syncthreads();

        // ---- issue cp.async for next token (hidden behind both GEMMs) ----
        {
            int tn = t + gstep;
            if (tn < ntok) {
                const char* src = reinterpret_cast<const char*>(x + (size_t)tn * TOK);
                #pragma unroll
                for (int it = 0; it < 16; it++) {
                    int i = tid + it * 256;
                    CP_ASYNC16(x32b + (uint32_t)i * 16u, src + (size_t)i * 16);
                }
            }
            asm volatile("cp.async.commit_group;" ::: "memory");
        }

        // ---- GEMM1 (fp16 acc): T[m1][n2] = sum_m2 X[m1][m2] * V[m2][n2] ----
        uint32_t c1[4][4][2];
        #pragma unroll
        for (int i = 0; i < 4; i++)
            #pragma unroll
            for (int j = 0; j < 4; j++) { c1[i][j][0] = 0u; c1[i][j][1] = 0u; }

        #pragma unroll
        for (int ks = 0; ks < 8; ks++) {
            uint32_t koff = ((uint32_t)(32 * ks) + lk) ^ lsw;
            uint32_t a[4][4];
            #pragma unroll
            for (int mt = 0; mt < 4; mt++)
                LDMX4(a[mt],
                      sb + OFF_X16 + (uint32_t)(m0 + mt * 16 + lrow) * 256u + koff);
            #pragma unroll
            for (int mt = 0; mt < 4; mt++) {
                MMA16816H(c1[mt][0], a[mt], vst[ks][0][0], vst[ks][0][2]);
                MMA16816H(c1[mt][1], a[mt], vst[ks][0][1], vst[ks][0][3]);
                MMA16816H(c1[mt][2], a[mt], vst[ks][1][0], vst[ks][1][2]);
                MMA16816H(c1[mt][3], a[mt], vst[ks][1][1], vst[ks][1][3]);
            }
        }

        // ---- store T natural [m1][n2]: acc regs ARE the half2 pairs ----
        #pragma unroll
        for (int mt = 0; mt < 4; mt++) {
            #pragma unroll
            for (int nt = 0; nt < 4; nt++) {
                int m1 = m0 + mt * 16 + g;
                int n2 = n0 + nt * 8 + 2 * tg4;
                *reinterpret_cast<uint32_t*>(
                    th + m1 * 128 + (n2 ^ ((m1 & 7) << 3))) = c1[mt][nt][0];
                *reinterpret_cast<uint32_t*>(
                    th + (m1 + 8) * 128 + (n2 ^ (((m1 + 8) & 7) << 3))) = c1[mt][nt][1];
            }
        }
        __syncthreads();

        // ---- GEMM2 (fp32 acc): Y^T[n2][n1] = sum_m1 T^T[n2][m1] * Ut[n1][m1] ----
        float c[4][4][4];
        #pragma unroll
        for (int i = 0; i < 4; i++)
            #pragma unroll
            for (int j = 0; j < 4; j++)
                #pragma unroll
                for (int q = 0; q < 4; q++) c[i][j][q] = 0.f;

        #pragma unroll
        for (int ks = 0; ks < 8; ks++) {
            uint32_t a[4][4];
            #pragma unroll
            for (int at = 0; at < 4; at++) {
                uint32_t srow = (uint32_t)(16 * ks) + arow;
                uint32_t scol = (uint32_t)(a20 + at * 16) + acolh;
                LDMX4T(a[at], sb + OFF_T + srow * 256u + ((scol * 2u) ^ lsw));
            }
            #pragma unroll
            for (int at = 0; at < 4; at++) {
                MMA16816(c[at][0], a[at], ust[ks][0][0], ust[ks][0][2]);
                MMA16816(c[at][1], a[at], ust[ks][0][1], ust[ks][0][3]);
                MMA16816(c[at][2], a[at], ust[ks][1][0], ust[ks][1][2]);
                MMA16816(c[at][3], a[at], ust[ks][1][1], ust[ks][1][3]);
            }
        }

        // ---- epilogue: C = Y^T[n2][n1] -> out[n1*128+n2] (scattered STG.32) ----
        {
            float* o = out + (size_t)t * TOK;
            #pragma unroll
            for (int at = 0; at < 4; at++) {
                int n2a = a20 + at * 16 + g;
                #pragma unroll
                for (int bt = 0; bt < 4; bt++) {
                    int n1a = b20 + bt * 8 + 2 * tg4;
                    __stcs(o + n1a * 128 + n2a,           c[at][bt][0]);
                    __stcs(o + (n1a + 1) * 128 + n2a,     c[at][bt][1]);
                    __stcs(o + n1a * 128 + n2a + 8,       c[at][bt][2]);
                    __stcs(o + (n1a + 1) * 128 + n2a + 8, c[at][bt][3]);
                }
            }
        }

        // next token's X32 must be resident before convert; also protects T/X16
        asm volatile("cp.async.wait_group 0;" ::: "memory");
        __syncthreads();
    }
}

// ---------------------------------------------------------------------------
extern "C" void kernel_launch(void* const* d_in, const int* in_sizes, int n_in,
                              void* d_out, int out_size) {
    (void)n_in; (void)out_size;
    const float* x = (const float*)d_in[0];
    const float* U = (const float*)d_in[1];
    const float* V = (const float*)d_in[2];
    float* out = (float*)d_out;
    const int ntok = in_sizes[0] / TOK;

    static int sm_count = 0;
    if (sm_count == 0) {
        cudaDeviceGetAttribute(&sm_count, cudaDevAttrMultiProcessorCount, 0);
        if (sm_count <= 0) sm_count = 148;
        cudaFuncSetAttribute(kron_main, cudaFuncAttributeMaxDynamicSharedMemorySize,
                             SMEM_BYTES);
    }
    int grid = sm_count < ntok ? sm_count : ntok;

    kron_setup<<<64, 256>>>(U, V);
    kron_main<<<grid, 256, SMEM_BYTES>>>(x, out, ntok);
}